// round 13
// baseline (speedup 1.0000x reference)
#include <cuda_runtime.h>

// Aggre_81226421502275: y[n] = mean_k( relu(mailbox[n,k,:]@W1 + b1) @ W2 + b2 )
// N=500000, K=16, F_IN=7, F_HID=40, F_OUT=3. fp32.
//
// R13: fma-work-bound regime; raise occupancy + cut issue overhead.
//  - 4 threads/node, each owns 10 hidden units (5 packed pairs) -> weight regs 140->70
//  - weights/bias register-resident (hoisted out of t-loop by ptxas, as in R12)
//  - mailbox staged to shared DUPLICATED ({x,x},{y,y},...) -> LDS.64 returns a
//    broadcast-packed f32x2 operand directly (kills ~224 MOVs/thread)
//  - bias folded into first fma2 of each chain (no acc-init MOVs)
//  - row stride 228 floats: conflict-free for 8 node-groups/warp, 16B-aligned
//  - __launch_bounds__(128,3): 170-reg ceiling (est. need ~130) -> 3 CTAs/SM

#define KK    16
#define FIN   7
#define FHID  40
#define FOUT  3
#define NPB   32            // nodes per block (4 threads each)
#define TPB   128
#define ROWSD 228           // duplicated row stride in floats (224 used + 4 pad)
#define JPT   5             // hidden pairs per thread (40/2/4)

typedef unsigned long long u64;
typedef unsigned int       u32;

__device__ __forceinline__ u64 pack2(float x, float y) {
    u64 r; asm("mov.b64 %0, {%1, %2};" : "=l"(r) : "f"(x), "f"(y)); return r;
}
__device__ __forceinline__ void unpack2(u64 v, float &x, float &y) {
    asm("mov.b64 {%0, %1}, %2;" : "=f"(x), "=f"(y) : "l"(v));
}
__device__ __forceinline__ u64 fma2(u64 a, u64 b, u64 c) {
    u64 d; asm("fma.rn.f32x2 %0, %1, %2, %3;" : "=l"(d) : "l"(a), "l"(b), "l"(c)); return d;
}
__device__ __forceinline__ u64 add2(u64 a, u64 b) {
    u64 d; asm("add.rn.f32x2 %0, %1, %2;" : "=l"(d) : "l"(a), "l"(b)); return d;
}
// packed relu: zero each fp32 half whose sign bit is set (alu pipe: SHF+LOP3 per half)
__device__ __forceinline__ u64 relu2(u64 v) {
    u32 lo, hi;
    asm("mov.b64 {%0, %1}, %2;" : "=r"(lo), "=r"(hi) : "l"(v));
    lo &= ~(u32)((int)lo >> 31);
    hi &= ~(u32)((int)hi >> 31);
    u64 r; asm("mov.b64 %0, {%1, %2};" : "=l"(r) : "r"(lo), "r"(hi));
    return r;
}

__global__ __launch_bounds__(TPB, 3)
void aggre_mlp_kernel(const float* __restrict__ mailbox,
                      const float* __restrict__ W1,
                      const float* __restrict__ b1,
                      const float* __restrict__ W2,
                      const float* __restrict__ b2,
                      float* __restrict__ out,
                      int N)
{
    __shared__ float smb[NPB * ROWSD];      // duplicated mailbox rows
    __shared__ u64   sW1p[FIN * (FHID/2)];  // [f][jp] = (W1[f][2jp], W1[f][2jp+1])
    __shared__ u64   sb1p[FHID / 2];
    __shared__ float sW2[FHID * FOUT];      // row-major [j][o]
    __shared__ float sb2[FOUT];

    const int tid = threadIdx.x;

    // ---- weight prep ----
    for (int i = tid; i < FIN * (FHID / 2); i += TPB)
        sW1p[i] = pack2(W1[2 * i], W1[2 * i + 1]);
    if (tid < FHID / 2) sb1p[tid] = pack2(b1[2 * tid], b1[2 * tid + 1]);
    for (int i = tid; i < FHID * FOUT; i += TPB) sW2[i] = W2[i];
    if (tid < FOUT) sb2[tid] = b2[tid];

    // ---- stage mailbox duplicated: 32 nodes x 112 floats -> {x,x,y,y,...} ----
    const int node0 = blockIdx.x * NPB;
    const int valid = min(NPB, N - node0);
    const int vq    = valid * (KK * FIN / 4);               // valid float4 count
    const float4* gsrc = reinterpret_cast<const float4*>(mailbox + (long long)node0 * (KK * FIN));
#pragma unroll
    for (int i = 0; i < (NPB * KK * FIN / 4) / TPB; i++) { // 7 iterations
        int idx = i * TPB + tid;
        if (idx >= vq) idx = vq - 1;                        // clamp (benign dup stores)
        const float4 v = gsrc[idx];
        const int fidx = idx * 4;
        const int node = fidx / (KK * FIN);
        const int off  = fidx - node * (KK * FIN);
        float4* d = reinterpret_cast<float4*>(&smb[node * ROWSD + 2 * off]);
        d[0] = make_float4(v.x, v.x, v.y, v.y);
        d[1] = make_float4(v.z, v.z, v.w, v.w);
    }
    __syncthreads();

    // ---- compute: 4 threads/node, each 5 hidden pairs ----
    const int nl   = tid >> 2;                 // local node 0..31
    const int jh   = tid & 3;                  // hidden quarter
    const int n    = node0 + nl;
    const bool live = (n < N);
    const int nlc  = live ? nl : 0;
    const int jpb  = jh * JPT;                 // first hidden pair index

    // Register-resident weights/bias for this thread's 5 pairs (hoisted by ptxas).
    u64 w[FIN][JPT];
    u64 bb[JPT];
#pragma unroll
    for (int q = 0; q < JPT; q++) {
        bb[q] = sb1p[jpb + q];
#pragma unroll
        for (int f = 0; f < FIN; f++) w[f][q] = sW1p[f * (FHID / 2) + jpb + q];
    }

    u64 hs[JPT];
#pragma unroll
    for (int q = 0; q < JPT; q++) hs[q] = 0ull;

    const u64* mrow = reinterpret_cast<const u64*>(&smb[nlc * ROWSD]);

#pragma unroll 1
    for (int t = 0; t < KK / 2; t++) {
        // two messages, features pre-broadcast-packed in shared
        u64 m0[FIN], m1[FIN];
#pragma unroll
        for (int f = 0; f < FIN; f++) {
            m0[f] = mrow[t * (2 * FIN) + f];
            m1[f] = mrow[t * (2 * FIN) + FIN + f];
        }

#pragma unroll
        for (int q = 0; q < JPT; q++) {
            u64 a0 = fma2(m0[0], w[0][q], bb[q]);
            u64 a1 = fma2(m1[0], w[0][q], bb[q]);
#pragma unroll
            for (int f = 1; f < FIN; f++) {
                a0 = fma2(m0[f], w[f][q], a0);
                a1 = fma2(m1[f], w[f][q], a1);
            }
            hs[q] = add2(hs[q], add2(relu2(a0), relu2(a1)));
        }
    }

    // ---- layer 2 on this thread's 10 hidden units, combine across the quad ----
    float y0 = 0.0f, y1 = 0.0f, y2 = 0.0f;
#pragma unroll
    for (int q = 0; q < JPT; q++) {
        const int j = 2 * (jpb + q);
        float h0, h1;
        unpack2(hs[q], h0, h1);
        y0 = fmaf(h0, sW2[j * FOUT + 0], y0);
        y1 = fmaf(h0, sW2[j * FOUT + 1], y1);
        y2 = fmaf(h0, sW2[j * FOUT + 2], y2);
        y0 = fmaf(h1, sW2[(j + 1) * FOUT + 0], y0);
        y1 = fmaf(h1, sW2[(j + 1) * FOUT + 1], y1);
        y2 = fmaf(h1, sW2[(j + 1) * FOUT + 2], y2);
    }

    y0 += __shfl_xor_sync(0xffffffffu, y0, 1);
    y1 += __shfl_xor_sync(0xffffffffu, y1, 1);
    y2 += __shfl_xor_sync(0xffffffffu, y2, 1);
    y0 += __shfl_xor_sync(0xffffffffu, y0, 2);
    y1 += __shfl_xor_sync(0xffffffffu, y1, 2);
    y2 += __shfl_xor_sync(0xffffffffu, y2, 2);

    if (live && jh == 0) {
        const float inv = 1.0f / (float)KK;
        out[n * FOUT + 0] = fmaf(y0, inv, sb2[0]);
        out[n * FOUT + 1] = fmaf(y1, inv, sb2[1]);
        out[n * FOUT + 2] = fmaf(y2, inv, sb2[2]);
    }
}

extern "C" void kernel_launch(void* const* d_in, const int* in_sizes, int n_in,
                              void* d_out, int out_size)
{
    const float* mailbox = (const float*)d_in[0];
    const float* W1      = (const float*)d_in[1];
    const float* b1      = (const float*)d_in[2];
    const float* W2      = (const float*)d_in[3];
    const float* b2      = (const float*)d_in[4];
    float*       out     = (float*)d_out;

    const int N = in_sizes[0] / (KK * FIN);
    const int blocks = (N + NPB - 1) / NPB;
    aggre_mlp_kernel<<<blocks, TPB>>>(mailbox, W1, b1, W2, b2, out, N);
}